// round 15
// baseline (speedup 1.0000x reference)
#include <cuda_runtime.h>
#include <cuda_fp16.h>
#include <cstdint>
#include <cstddef>

// ---------------------------------------------------------------------------
// Problem constants
// ---------------------------------------------------------------------------
static constexpr int IN_DIM  = 4096;     // K
static constexpr int OUT_DIM = 32768;    // N
static constexpr int BATCH   = 4096;     // M
static constexpr float WSCALE = 8192.0f; // 2^13: lift W out of fp16 subnormals
static constexpr float EPSV   = 1e-8f;
static constexpr float WEPS2  = (WSCALE * EPSV) * (WSCALE * EPSV);

// GEMM tiling: 128x128 CTA tile, BK=64/stage, 3-stage cp.async ring,
// 2 CTAs/SM, 4 warps, warp tile 64x64. PERSISTENT: grid=304, each CTA walks
// tiles t = bid + 304*i; the ring runs continuously across tile boundaries.
// (tcgen05 unreachable: harness builds via compute_103 virtual PTX.)
static constexpr int BM = 128;
static constexpr int BN = 128;
static constexpr int BK = 64;                      // halfs per row per stage
static constexpr int NSTAGES = 3;
static constexpr int KITERS = IN_DIM / BK;         // 64
static constexpr int NTILES = (BATCH / BM) * (OUT_DIM / BN);   // 8192
static constexpr int GRID   = 304;                 // 2 x 152 SMs
static constexpr int ASTAGE = BM * 128;            // 16 KB
static constexpr int BSTAGE = BN * 128;            // 16 KB
static constexpr int STAGE  = ASTAGE + BSTAGE;     // 32 KB
static constexpr int SMEM_TOTAL = NSTAGES * STAGE; // 96 KB (x2 CTAs = 192 KB)

// ---------------------------------------------------------------------------
// Device-global scratch (allocation-free rule)
// ---------------------------------------------------------------------------
__device__ __align__(256) __half g_x16[(size_t)BATCH * IN_DIM];     // 32 MB
__device__ __align__(256) __half g_w16t[(size_t)OUT_DIM * IN_DIM];  // 256 MB
__device__ float  g_inv_xn[BATCH];
__device__ float  g_wn2[OUT_DIM];

// ---------------------------------------------------------------------------
// PTX helpers
// ---------------------------------------------------------------------------
__device__ __forceinline__ uint32_t smem_u32(const void* p) {
    return (uint32_t)__cvta_generic_to_shared(p);
}

#define CP_ASYNC16(dst, src) \
    asm volatile("cp.async.cg.shared.global [%0], [%1], 16;" :: "r"(dst), "l"(src) : "memory")
#define CP_COMMIT()  asm volatile("cp.async.commit_group;" ::: "memory")
#define CP_WAIT1()   asm volatile("cp.async.wait_group 1;" ::: "memory")

__device__ __forceinline__ void ldsm_x4(uint32_t* r, uint32_t addr) {
    asm volatile("ldmatrix.sync.aligned.m8n8.x4.shared.b16 {%0,%1,%2,%3}, [%4];"
                 : "=r"(r[0]), "=r"(r[1]), "=r"(r[2]), "=r"(r[3])
                 : "r"(addr));
}

__device__ __forceinline__ void mma16816(float* c, const uint32_t* a, const uint32_t* b) {
    asm volatile(
        "mma.sync.aligned.m16n8k16.row.col.f32.f16.f16.f32 "
        "{%0,%1,%2,%3}, {%4,%5,%6,%7}, {%8,%9}, {%0,%1,%2,%3};"
        : "+f"(c[0]), "+f"(c[1]), "+f"(c[2]), "+f"(c[3])
        : "r"(a[0]), "r"(a[1]), "r"(a[2]), "r"(a[3]), "r"(b[0]), "r"(b[1]));
}

// ---------------------------------------------------------------------------
// Kernel 1: x (f32) -> g_x16 (fp16) + row inverse norms; also zeroes g_wn2
// (atomics accumulate per graph replay). One block per row.
// ---------------------------------------------------------------------------
__global__ __launch_bounds__(256) void k_prep_x(const float* __restrict__ x) {
    __shared__ float red[8];
    int b = blockIdx.x;
    int t = threadIdx.x;
    if (b < OUT_DIM / 256) g_wn2[b * 256 + t] = 0.0f;   // fold-in zeroing
    const float4* xr = (const float4*)(x + (size_t)b * IN_DIM);
    __half2* dst = (__half2*)(g_x16 + (size_t)b * IN_DIM);
    float s = 0.0f;
#pragma unroll
    for (int i = 0; i < 4; i++) {
        int e4 = t + 256 * i;
        float4 v = xr[e4];
        s += v.x * v.x + v.y * v.y + v.z * v.z + v.w * v.w;
        dst[e4 * 2 + 0] = __floats2half2_rn(v.x, v.y);
        dst[e4 * 2 + 1] = __floats2half2_rn(v.z, v.w);
    }
#pragma unroll
    for (int o = 16; o > 0; o >>= 1) s += __shfl_down_sync(0xffffffffu, s, o);
    if ((t & 31) == 0) red[t >> 5] = s;
    __syncthreads();
    if (t == 0) {
        float tot = 0.0f;
#pragma unroll
        for (int w = 0; w < 8; w++) tot += red[w];
        g_inv_xn[b] = 1.0f / fmaxf(sqrtf(tot), EPSV);
    }
}

// ---------------------------------------------------------------------------
// Kernel 2: transpose + scale W[k][o] -> g_w16t[o][k] (fp16 * WSCALE),
// fused column sum-sq. Tile: 64 k x 32 o. Writes are full 128B half2 rows.
// ---------------------------------------------------------------------------
__global__ __launch_bounds__(256) void k_transpose_w(const float* __restrict__ w) {
    __shared__ float tile[32][66];        // [o][k], padded
    const int o0 = blockIdx.x * 32;
    const int k0 = blockIdx.y * 64;
    const int t = threadIdx.x;
    const int warp = t >> 5;
    const int lane = t & 31;
#pragma unroll
    for (int i = 0; i < 8; i++) {
        int idx = t + 256 * i;            // 0..2047
        int r = idx >> 5;                 // k within tile 0..63
        int c = idx & 31;                 // o within tile
        tile[c][r] = w[(size_t)(k0 + r) * OUT_DIM + o0 + c];
    }
    __syncthreads();
#pragma unroll
    for (int it = 0; it < 4; it++) {
        const int ro = warp + 8 * it;     // o within tile 0..31
        float2 v = *(const float2*)&tile[ro][2 * lane];
        __half2 h = __floats2half2_rn(v.x * WSCALE, v.y * WSCALE);
        ((__half2*)(g_w16t + (size_t)(o0 + ro) * IN_DIM + k0))[lane] = h;
        float2 f = __half22float2(h);
        float s = f.x * f.x + f.y * f.y;
#pragma unroll
        for (int off = 16; off > 0; off >>= 1)
            s += __shfl_down_sync(0xffffffffu, s, off);
        if (lane == 0) atomicAdd(&g_wn2[o0 + ro], s);
    }
}

// ---------------------------------------------------------------------------
// Kernel 3: PERSISTENT pipelined HMMA GEMM (128x128x64, 3 stages).
// 128 threads = 4 warps (2Mx2N), warp tile 64x64.
// The cp.async ring + tail-sync run continuously across tile boundaries:
// the load cursor stays 2 chunks ahead globally, so a tile's epilogue is
// covered by the already-loaded first stages of the next tile.
// ---------------------------------------------------------------------------
__global__ __launch_bounds__(128, 2) void k_gemm(float* __restrict__ out) {
    extern __shared__ __align__(128) char smem[];
    const uint32_t sbase = smem_u32(smem);
    const int tid  = threadIdx.x;
    const int wid  = tid >> 5;
    const int lane = tid & 31;

    const int m_w = (wid & 1) * 64;
    const int n_w = (wid >> 1) * 64;

    // ---- producer addressing: 16 x 16B cp.async per thread per stage ----
    const int r0 = tid >> 3;
    const int j  = tid & 7;
    const uint32_t swj = (uint32_t)((j ^ (r0 & 7)) * 16);   // swizzled chunk
    const size_t rows16 = (size_t)16 * IN_DIM;
    const uint32_t dA = sbase + (uint32_t)(r0 * 128) + swj;
    const uint32_t dB = dA + ASTAGE;

    // load-cursor state: tile lt, k-chunk lk (globally 2 chunks ahead)
    int lt = blockIdx.x;
    const __half* srcA = g_x16  + (size_t)((lt & 31) * BM + r0) * IN_DIM + j * 8;
    const __half* srcB = g_w16t + (size_t)((lt >> 5) * BN + r0) * IN_DIM + j * 8;

#define LOAD_STAGE(slot, kk) do {                                            \
        const uint32_t so = (uint32_t)(slot) * STAGE;                        \
        const int koff = (kk) * BK;                                          \
        _Pragma("unroll")                                                    \
        for (int i = 0; i < 8; i++)                                          \
            CP_ASYNC16(dA + so + (uint32_t)(i * 16 * 128),                   \
                       (const void*)(srcA + i * rows16 + koff));             \
        _Pragma("unroll")                                                    \
        for (int i = 0; i < 8; i++)                                          \
            CP_ASYNC16(dB + so + (uint32_t)(i * 16 * 128),                   \
                       (const void*)(srcB + i * rows16 + koff));             \
    } while (0)

    LOAD_STAGE(0, 0); CP_COMMIT();
    LOAD_STAGE(1, 1); CP_COMMIT();
    int lk = 2;

    // ---- ldmatrix lane bases (row&7 == lane&7 everywhere -> fixed XOR) ----
    const uint32_t sw   = (uint32_t)(lane & 7);
    const uint32_t hi_a = (uint32_t)(lane >> 4);          // A k-chunk parity
    const uint32_t hi_b = (uint32_t)((lane >> 3) & 1);    // B k-chunk parity
    const uint32_t arow = (uint32_t)(m_w + ((lane >> 3) & 1) * 8 + (lane & 7));
    const uint32_t brow = (uint32_t)(n_w + (lane >> 4) * 8 + (lane & 7));
    const uint32_t aBase = arow * 128;            // + mi*2048 + chunk*16
    const uint32_t bBase = brow * 128 + ASTAGE;   // + p*2048  + chunk*16

#define LD_AFRAGS(stg, buf, s) do {                                          \
        const uint32_t ca = ((uint32_t)(2 * (s)) + hi_a) ^ sw;               \
        _Pragma("unroll")                                                    \
        for (int mi = 0; mi < 4; mi++)                                       \
            ldsm_x4(afr[buf][mi],                                            \
                    (stg) + aBase + (uint32_t)(mi * 2048) + ca * 16);        \
    } while (0)
#define LD_BFRAGS(stg, buf, s) do {                                          \
        const uint32_t cb = ((uint32_t)(2 * (s)) + hi_b) ^ sw;               \
        _Pragma("unroll")                                                    \
        for (int p = 0; p < 4; p++) {                                        \
            uint32_t r[4];                                                   \
            ldsm_x4(r, (stg) + bBase + (uint32_t)(p * 2048) + cb * 16);      \
            bfr[buf][2 * p][0] = r[0];     bfr[buf][2 * p][1] = r[1];        \
            bfr[buf][2 * p + 1][0] = r[2]; bfr[buf][2 * p + 1][1] = r[3];    \
        }                                                                    \
    } while (0)

    float acc[4][8][4];
#pragma unroll
    for (int i = 0; i < 4; i++)
#pragma unroll
        for (int nn = 0; nn < 8; nn++)
#pragma unroll
            for (int e = 0; e < 4; e++) acc[i][nn][e] = 0.0f;

    uint32_t afr[2][4][4];
    uint32_t bfr[2][8][2];

    // Prologue: stage 0 visible, prefetch its step-0 frags into buf 0.
    CP_WAIT1();
    __syncthreads();
    LD_AFRAGS(sbase, 0, 0);
    LD_BFRAGS(sbase, 0, 0);

    int cslot = 0;   // stage being computed this iteration
    int lslot = 2;   // ring slot receiving the next load

#pragma unroll 1
    for (int tile = blockIdx.x; tile < NTILES; tile += GRID) {
        const int m0 = (tile & 31) * BM;
        const int n0 = (tile >> 5) * BN;
        const bool last_tile = (tile + GRID >= NTILES);

#pragma unroll 1
        for (int ki = 0; ki < KITERS; ki++) {
            const uint32_t st = sbase + (uint32_t)cslot * STAGE;

            // steps: LDSM(s+1) overlaps MMA(s); step-0 frags from prev tail
#pragma unroll
            for (int s = 0; s < 4; s++) {
                const int buf = s & 1;
                if (s < 3) {
                    LD_AFRAGS(st, buf ^ 1, s + 1);
                    LD_BFRAGS(st, buf ^ 1, s + 1);
                }
#pragma unroll
                for (int mi = 0; mi < 4; mi++)
#pragma unroll
                    for (int ni = 0; ni < 8; ni++)
                        mma16816(acc[mi][ni], afr[buf][mi], bfr[buf][ni]);
            }

            // advance load cursor across tile boundaries
            if (lk == KITERS) {
                lt += GRID;
                lk = 0;
                if (lt < NTILES) {
                    srcA = g_x16  + (size_t)((lt & 31) * BM + r0) * IN_DIM + j * 8;
                    srcB = g_w16t + (size_t)((lt >> 5) * BN + r0) * IN_DIM + j * 8;
                }
            }
            if (lt < NTILES) LOAD_STAGE(lslot, lk);
            lk++;
            CP_COMMIT();   // unconditional: keeps wait_group arithmetic exact
            if (++lslot == NSTAGES) lslot = 0;
            if (++cslot == NSTAGES) cslot = 0;

            // tail: wait+barrier+prefetch hide behind the queued MMA backlog
            if (!(last_tile && ki + 1 == KITERS)) {
                CP_WAIT1();          // next chunk's stage is complete
                __syncthreads();     // visibility + slot-reuse ordering
                const uint32_t stn = sbase + (uint32_t)cslot * STAGE;
                LD_AFRAGS(stn, 0, 0);
                LD_BFRAGS(stn, 0, 0);
            }
        }

        // ---- epilogue: cosine scaling, float2 stores; next tile's step-0
        // frags are already in buf0, so the mainloop resumes immediately ----
        {
            const int g = lane >> 2;
            const int q = lane & 3;
            float wn0[8], wn1[8];
#pragma unroll
            for (int ni = 0; ni < 8; ni++) {
                const int c = n0 + n_w + ni * 8 + q * 2;
                wn0[ni] = rsqrtf(fmaxf(g_wn2[c], WEPS2));
                wn1[ni] = rsqrtf(fmaxf(g_wn2[c + 1], WEPS2));
            }
#pragma unroll
            for (int mi = 0; mi < 4; mi++) {
                const int r = m0 + m_w + mi * 16 + g;
                const float sx0 = g_inv_xn[r];
                const float sx1 = g_inv_xn[r + 8];
#pragma unroll
                for (int ni = 0; ni < 8; ni++) {
                    const int c = n0 + n_w + ni * 8 + q * 2;
                    float2 v0 = make_float2(acc[mi][ni][0] * sx0 * wn0[ni],
                                            acc[mi][ni][1] * sx0 * wn1[ni]);
                    float2 v1 = make_float2(acc[mi][ni][2] * sx1 * wn0[ni],
                                            acc[mi][ni][3] * sx1 * wn1[ni]);
                    *(float2*)&out[(size_t)r * OUT_DIM + c] = v0;
                    *(float2*)&out[(size_t)(r + 8) * OUT_DIM + c] = v1;
                }
            }
        }
#pragma unroll
        for (int i = 0; i < 4; i++)
#pragma unroll
            for (int nn = 0; nn < 8; nn++)
#pragma unroll
                for (int e = 0; e < 4; e++) acc[i][nn][e] = 0.0f;
    }
#undef LOAD_STAGE
#undef LD_AFRAGS
#undef LD_BFRAGS
}

// ---------------------------------------------------------------------------
// Launch
// ---------------------------------------------------------------------------
extern "C" void kernel_launch(void* const* d_in, const int* in_sizes, int n_in,
                              void* d_out, int out_size) {
    const float* x = (const float*)d_in[0];       // (4096, 4096)
    const float* w = (const float*)d_in[1];       // (4096, 32768)
    float* out = (float*)d_out;                   // (4096, 32768)

    cudaFuncSetAttribute(k_gemm, cudaFuncAttributeMaxDynamicSharedMemorySize,
                         SMEM_TOTAL);

    k_prep_x<<<BATCH, 256>>>(x);
    k_transpose_w<<<dim3(OUT_DIM / 32, IN_DIM / 64), 256>>>(w);
    k_gemm<<<GRID, 128, SMEM_TOTAL>>>(out);
}

// round 16
// speedup vs baseline: 1.1172x; 1.1172x over previous
#include <cuda_runtime.h>
#include <cuda_fp16.h>
#include <cstdint>
#include <cstddef>

// ---------------------------------------------------------------------------
// Problem constants
// ---------------------------------------------------------------------------
static constexpr int IN_DIM  = 4096;     // K
static constexpr int OUT_DIM = 32768;    // N
static constexpr int BATCH   = 4096;     // M
static constexpr float WSCALE = 8192.0f; // 2^13: lift W out of fp16 subnormals
static constexpr float EPSV   = 1e-8f;
static constexpr float WEPS2  = (WSCALE * EPSV) * (WSCALE * EPSV);

// GEMM tiling: 128x128 CTA, BK=64/stage, 3-stage cp.async ring, 2 CTAs/SM,
// 4 warps, warp tile 64x64. (tcgen05 unreachable: compute_103 virtual PTX.)
// NOTE (R10 post-mortem): persistent-CTA variant regressed (+248us) — CTA
// churn is cheap here, lockstep is expensive. Non-persistent is the winner.
static constexpr int BM = 128;
static constexpr int BN = 128;
static constexpr int BK = 64;                      // halfs per row per stage
static constexpr int NSTAGES = 3;
static constexpr int KITERS = IN_DIM / BK;         // 64
static constexpr int ASTAGE = BM * 128;            // 16 KB
static constexpr int BSTAGE = BN * 128;            // 16 KB
static constexpr int STAGE  = ASTAGE + BSTAGE;     // 32 KB
static constexpr int SMEM_TOTAL = NSTAGES * STAGE; // 96 KB (x2 CTAs = 192 KB)

// ---------------------------------------------------------------------------
// Device-global scratch (allocation-free rule)
// ---------------------------------------------------------------------------
__device__ __align__(256) __half g_x16[(size_t)BATCH * IN_DIM];     // 32 MB
__device__ __align__(256) __half g_w16t[(size_t)OUT_DIM * IN_DIM];  // 256 MB
__device__ float  g_inv_xn[BATCH];
__device__ float  g_wn2[OUT_DIM];

// ---------------------------------------------------------------------------
// PTX helpers
// ---------------------------------------------------------------------------
__device__ __forceinline__ uint32_t smem_u32(const void* p) {
    return (uint32_t)__cvta_generic_to_shared(p);
}

#define CP_ASYNC16(dst, src) \
    asm volatile("cp.async.cg.shared.global [%0], [%1], 16;" :: "r"(dst), "l"(src) : "memory")
#define CP_COMMIT()  asm volatile("cp.async.commit_group;" ::: "memory")
#define CP_WAIT1()   asm volatile("cp.async.wait_group 1;" ::: "memory")

__device__ __forceinline__ void ldsm_x4(uint32_t* r, uint32_t addr) {
    asm volatile("ldmatrix.sync.aligned.m8n8.x4.shared.b16 {%0,%1,%2,%3}, [%4];"
                 : "=r"(r[0]), "=r"(r[1]), "=r"(r[2]), "=r"(r[3])
                 : "r"(addr));
}

__device__ __forceinline__ void mma16816(float* c, const uint32_t* a, const uint32_t* b) {
    asm volatile(
        "mma.sync.aligned.m16n8k16.row.col.f32.f16.f16.f32 "
        "{%0,%1,%2,%3}, {%4,%5,%6,%7}, {%8,%9}, {%0,%1,%2,%3};"
        : "+f"(c[0]), "+f"(c[1]), "+f"(c[2]), "+f"(c[3])
        : "r"(a[0]), "r"(a[1]), "r"(a[2]), "r"(a[3]), "r"(b[0]), "r"(b[1]));
}

// ---------------------------------------------------------------------------
// Kernel 1: x (f32) -> g_x16 (fp16) + row inverse norms; also zeroes g_wn2
// (atomics accumulate per graph replay). One block per row.
// ---------------------------------------------------------------------------
__global__ __launch_bounds__(256) void k_prep_x(const float* __restrict__ x) {
    __shared__ float red[8];
    int b = blockIdx.x;
    int t = threadIdx.x;
    if (b < OUT_DIM / 256) g_wn2[b * 256 + t] = 0.0f;   // fold-in zeroing
    const float4* xr = (const float4*)(x + (size_t)b * IN_DIM);
    __half2* dst = (__half2*)(g_x16 + (size_t)b * IN_DIM);
    float s = 0.0f;
#pragma unroll
    for (int i = 0; i < 4; i++) {
        int e4 = t + 256 * i;
        float4 v = xr[e4];
        s += v.x * v.x + v.y * v.y + v.z * v.z + v.w * v.w;
        dst[e4 * 2 + 0] = __floats2half2_rn(v.x, v.y);
        dst[e4 * 2 + 1] = __floats2half2_rn(v.z, v.w);
    }
#pragma unroll
    for (int o = 16; o > 0; o >>= 1) s += __shfl_down_sync(0xffffffffu, s, o);
    if ((t & 31) == 0) red[t >> 5] = s;
    __syncthreads();
    if (t == 0) {
        float tot = 0.0f;
#pragma unroll
        for (int w = 0; w < 8; w++) tot += red[w];
        g_inv_xn[b] = 1.0f / fmaxf(sqrtf(tot), EPSV);
    }
}

// ---------------------------------------------------------------------------
// Kernel 2: transpose + scale W[k][o] -> g_w16t[o][k] (fp16 * WSCALE),
// fused column sum-sq. Tile: 64 k x 32 o. float4 global reads (8 lanes/row),
// full 128B half2 row writes.
// ---------------------------------------------------------------------------
__global__ __launch_bounds__(256) void k_transpose_w(const float* __restrict__ w) {
    __shared__ float tile[32][66];        // [o][k], padded (2-way worst case)
    const int o0 = blockIdx.x * 32;
    const int k0 = blockIdx.y * 64;
    const int t = threadIdx.x;
    const int warp = t >> 5;
    const int lane = t & 31;
    // load: 64 k-rows x 32 o-cols, float4 per lane: 8 lanes cover one row
    {
        const int r8 = t >> 3;            // k row 0..31 (then +32)
        const int c4 = t & 7;             // float4 index within row
#pragma unroll
        for (int h = 0; h < 2; h++) {
            const int r = r8 + 32 * h;
            float4 v = *(const float4*)&w[(size_t)(k0 + r) * OUT_DIM + o0 + c4 * 4];
            tile[c4 * 4 + 0][r] = v.x;
            tile[c4 * 4 + 1][r] = v.y;
            tile[c4 * 4 + 2][r] = v.z;
            tile[c4 * 4 + 3][r] = v.w;
        }
    }
    __syncthreads();
    // write: each warp emits one o-row of 64 halfs (128B) per round
#pragma unroll
    for (int it = 0; it < 4; it++) {
        const int ro = warp + 8 * it;     // o within tile 0..31
        float2 v = *(const float2*)&tile[ro][2 * lane];
        __half2 h = __floats2half2_rn(v.x * WSCALE, v.y * WSCALE);
        ((__half2*)(g_w16t + (size_t)(o0 + ro) * IN_DIM + k0))[lane] = h;
        float2 f = __half22float2(h);
        float s = f.x * f.x + f.y * f.y;
#pragma unroll
        for (int off = 16; off > 0; off >>= 1)
            s += __shfl_down_sync(0xffffffffu, s, off);
        if (lane == 0) atomicAdd(&g_wn2[o0 + ro], s);
    }
}

// ---------------------------------------------------------------------------
// Kernel 3: pipelined HMMA GEMM (128x128x64, 3 stages, swizzled 128B rows)
// 128 threads = 4 warps (2 along M x 2 along N), warp tile 64x64.
// Tail-sync schedule: {wait, barrier, next-stage step-0 prefetch} execute at
// the END of each iteration, hidden behind the tensor-pipe MMA backlog, so
// the first MMA after loop-back has zero load dependency.  (= R9, proven)
// ---------------------------------------------------------------------------
__global__ __launch_bounds__(128, 2) void k_gemm(float* __restrict__ out) {
    extern __shared__ __align__(128) char smem[];
    const uint32_t sbase = smem_u32(smem);
    const int tid  = threadIdx.x;
    const int wid  = tid >> 5;
    const int lane = tid & 31;

    // N-major raster: consecutive CTAs share B; all of X stays L2-resident
    const int mt = blockIdx.x & 31;
    const int nt = blockIdx.x >> 5;
    const int m0 = mt * BM;
    const int n0 = nt * BN;

    const int m_w = (wid & 1) * 64;
    const int n_w = (wid >> 1) * 64;

    // ---- producer addressing: 16 x 16B cp.async per thread per stage ----
    const int r0 = tid >> 3;
    const int j  = tid & 7;
    const uint32_t swj = (uint32_t)((j ^ (r0 & 7)) * 16);   // swizzled chunk
    const __half* srcA = g_x16  + (size_t)(m0 + r0) * IN_DIM + j * 8;
    const __half* srcB = g_w16t + (size_t)(n0 + r0) * IN_DIM + j * 8;
    const size_t rows16 = (size_t)16 * IN_DIM;
    const uint32_t dA = sbase + (uint32_t)(r0 * 128) + swj;
    const uint32_t dB = dA + ASTAGE;

#define LOAD_STAGE(slot, kk) do {                                            \
        const uint32_t so = (uint32_t)(slot) * STAGE;                        \
        const int koff = (kk) * BK;                                          \
        _Pragma("unroll")                                                    \
        for (int i = 0; i < 8; i++)                                          \
            CP_ASYNC16(dA + so + (uint32_t)(i * 16 * 128),                   \
                       (const void*)(srcA + i * rows16 + koff));             \
        _Pragma("unroll")                                                    \
        for (int i = 0; i < 8; i++)                                          \
            CP_ASYNC16(dB + so + (uint32_t)(i * 16 * 128),                   \
                       (const void*)(srcB + i * rows16 + koff));             \
    } while (0)

    LOAD_STAGE(0, 0); CP_COMMIT();
    LOAD_STAGE(1, 1); CP_COMMIT();

    // ---- ldmatrix lane bases (row&7 == lane&7 everywhere -> fixed XOR) ----
    const uint32_t sw   = (uint32_t)(lane & 7);
    const uint32_t hi_a = (uint32_t)(lane >> 4);          // A k-chunk parity
    const uint32_t hi_b = (uint32_t)((lane >> 3) & 1);    // B k-chunk parity
    const uint32_t arow = (uint32_t)(m_w + ((lane >> 3) & 1) * 8 + (lane & 7));
    const uint32_t brow = (uint32_t)(n_w + (lane >> 4) * 8 + (lane & 7));
    const uint32_t aBase = arow * 128;            // + mi*2048 + chunk*16
    const uint32_t bBase = brow * 128 + ASTAGE;   // + p*2048  + chunk*16

#define LD_AFRAGS(stg, buf, s) do {                                          \
        const uint32_t ca = ((uint32_t)(2 * (s)) + hi_a) ^ sw;               \
        _Pragma("unroll")                                                    \
        for (int mi = 0; mi < 4; mi++)                                       \
            ldsm_x4(afr[buf][mi],                                            \
                    (stg) + aBase + (uint32_t)(mi * 2048) + ca * 16);        \
    } while (0)
#define LD_BFRAGS(stg, buf, s) do {                                          \
        const uint32_t cb = ((uint32_t)(2 * (s)) + hi_b) ^ sw;               \
        _Pragma("unroll")                                                    \
        for (int p = 0; p < 4; p++) {                                        \
            uint32_t r[4];                                                   \
            ldsm_x4(r, (stg) + bBase + (uint32_t)(p * 2048) + cb * 16);      \
            bfr[buf][2 * p][0] = r[0];     bfr[buf][2 * p][1] = r[1];        \
            bfr[buf][2 * p + 1][0] = r[2]; bfr[buf][2 * p + 1][1] = r[3];    \
        }                                                                    \
    } while (0)

    float acc[4][8][4];
#pragma unroll
    for (int i = 0; i < 4; i++)
#pragma unroll
        for (int nn = 0; nn < 8; nn++)
#pragma unroll
            for (int e = 0; e < 4; e++) acc[i][nn][e] = 0.0f;

    uint32_t afr[2][4][4];
    uint32_t bfr[2][8][2];

    // Prologue: stage 0 visible, prefetch its step-0 frags into buf 0.
    CP_WAIT1();
    __syncthreads();
    LD_AFRAGS(sbase, 0, 0);
    LD_BFRAGS(sbase, 0, 0);

    int cslot = 0;   // stage being computed this iteration
    int lslot = 2;   // ring slot receiving the next load
#pragma unroll 1
    for (int ki = 0; ki < KITERS; ki++) {
        const uint32_t st = sbase + (uint32_t)cslot * STAGE;

        // steps: LDSM(s+1) overlaps MMA(s); step-0 frags came from prev tail
#pragma unroll
        for (int s = 0; s < 4; s++) {
            const int buf = s & 1;
            if (s < 3) {
                LD_AFRAGS(st, buf ^ 1, s + 1);
                LD_BFRAGS(st, buf ^ 1, s + 1);
            }
#pragma unroll
            for (int mi = 0; mi < 4; mi++)
#pragma unroll
                for (int ni = 0; ni < 8; ni++)
                    mma16816(acc[mi][ni], afr[buf][mi], bfr[buf][ni]);
        }

        // issue next-stage loads (slot (ki-1)%3: reads finished last iter,
        // ordered by last iteration's tail barrier)
        if (ki + 2 < KITERS) LOAD_STAGE(lslot, ki + 2);
        CP_COMMIT();   // unconditional: keeps wait_group arithmetic exact
        if (++lslot == NSTAGES) lslot = 0;
        if (++cslot == NSTAGES) cslot = 0;

        // tail: wait+barrier+prefetch hide behind the queued MMA backlog
        if (ki + 1 < KITERS) {
            CP_WAIT1();          // stage ki+1 complete (ki+2 may be in flight)
            __syncthreads();     // visibility + slot-reuse ordering
            const uint32_t stn = sbase + (uint32_t)cslot * STAGE;
            LD_AFRAGS(stn, 0, 0);
            LD_BFRAGS(stn, 0, 0);
        }
    }

    // ---- epilogue: cosine scaling (inv wnorm via rsqrt), float2 stores ----
    const int g = lane >> 2;
    const int q = lane & 3;
    float wn0[8], wn1[8];
#pragma unroll
    for (int ni = 0; ni < 8; ni++) {
        const int c = n0 + n_w + ni * 8 + q * 2;
        wn0[ni] = rsqrtf(fmaxf(g_wn2[c], WEPS2));
        wn1[ni] = rsqrtf(fmaxf(g_wn2[c + 1], WEPS2));
    }
#pragma unroll
    for (int mi = 0; mi < 4; mi++) {
        const int r = m0 + m_w + mi * 16 + g;
        const float sx0 = g_inv_xn[r];
        const float sx1 = g_inv_xn[r + 8];
#pragma unroll
        for (int ni = 0; ni < 8; ni++) {
            const int c = n0 + n_w + ni * 8 + q * 2;
            float2 v0 = make_float2(acc[mi][ni][0] * sx0 * wn0[ni],
                                    acc[mi][ni][1] * sx0 * wn1[ni]);
            float2 v1 = make_float2(acc[mi][ni][2] * sx1 * wn0[ni],
                                    acc[mi][ni][3] * sx1 * wn1[ni]);
            *(float2*)&out[(size_t)r * OUT_DIM + c] = v0;
            *(float2*)&out[(size_t)(r + 8) * OUT_DIM + c] = v1;
        }
    }
#undef LOAD_STAGE
#undef LD_AFRAGS
#undef LD_BFRAGS
}

// ---------------------------------------------------------------------------
// Launch
// ---------------------------------------------------------------------------
extern "C" void kernel_launch(void* const* d_in, const int* in_sizes, int n_in,
                              void* d_out, int out_size) {
    const float* x = (const float*)d_in[0];       // (4096, 4096)
    const float* w = (const float*)d_in[1];       // (4096, 32768)
    float* out = (float*)d_out;                   // (4096, 32768)

    cudaFuncSetAttribute(k_gemm, cudaFuncAttributeMaxDynamicSharedMemorySize,
                         SMEM_TOTAL);

    k_prep_x<<<BATCH, 256>>>(x);
    k_transpose_w<<<dim3(OUT_DIM / 32, IN_DIM / 64), 256>>>(w);
    k_gemm<<<(BATCH / BM) * (OUT_DIM / BN), 128, SMEM_TOTAL>>>(out);
}